// round 5
// baseline (speedup 1.0000x reference)
#include <cuda_runtime.h>
#include <cstdint>
#include <cstddef>

#define BATCH   2
#define SEQ     2048
#define DMODEL  1024
#define NHEADS  16
#define NPHYS   8
#define DHEAD   64
#define ROWS    (BATCH * SEQ)          // 4096
#define QKVCOLS (3 * DMODEL)           // 3072

// Scratch (device globals: allocation-free contract). All tf32-bit arrays as uint32.
__device__ uint32_t g_xc[(size_t)ROWS * DMODEL];       // x converted to tf32 bits
__device__ uint32_t g_wqkvc[(size_t)DMODEL * QKVCOLS]; // Wqkv tf32
__device__ uint32_t g_wprojc[(size_t)DMODEL * DMODEL]; // Wproj tf32
__device__ uint32_t g_qkv[(size_t)ROWS * QKVCOLS];     // qkv (tf32 bits)
__device__ uint32_t g_att[(size_t)ROWS * DMODEL];      // attention out (tf32 bits)

__device__ __forceinline__ uint32_t f2tf(float x) {
    uint32_t r; asm("cvt.rna.tf32.f32 %0, %1;" : "=r"(r) : "f"(x)); return r;
}

// m16n8k8 tf32 MMA, D = A*B + D (in place)
__device__ __forceinline__ void mma8(float* c, const uint32_t* a, const uint32_t* b) {
    asm volatile(
        "mma.sync.aligned.m16n8k8.row.col.f32.tf32.tf32.f32 "
        "{%0,%1,%2,%3},{%4,%5,%6,%7},{%8,%9},{%0,%1,%2,%3};"
        : "+f"(c[0]), "+f"(c[1]), "+f"(c[2]), "+f"(c[3])
        : "r"(a[0]), "r"(a[1]), "r"(a[2]), "r"(a[3]), "r"(b[0]), "r"(b[1]));
}

// ---------------------------------------------------------------------------
// Elementwise fp32 -> tf32-bits conversion (vectorized)
// ---------------------------------------------------------------------------
__global__ void cvt_tf32_kernel(const float4* __restrict__ in, uint4* __restrict__ out, int n4) {
    int i = blockIdx.x * blockDim.x + threadIdx.x;
    if (i < n4) {
        float4 v = in[i];
        out[i] = make_uint4(f2tf(v.x), f2tf(v.y), f2tf(v.z), f2tf(v.w));
    }
}

// ---------------------------------------------------------------------------
// tf32 tensor-core GEMM: C[M,N] = A[M,K] @ B[K,N], A/B are tf32 bits.
// CTA 128x128, BK=32, 256 threads, 8 warps in 4(m) x 2(n) grid, warp tile 32x64.
// Smem (dynamic 70656B): As[2][128][36] m-major pad4, Bs[2][32][132] k-major pad4.
// CVT_OUT: emit tf32 bits; else raw fp32 bits.
// ---------------------------------------------------------------------------
template<bool CVT_OUT>
__global__ __launch_bounds__(256) void gemm_tc(
    const uint32_t* __restrict__ A, const uint32_t* __restrict__ B, uint32_t* __restrict__ C,
    int M, int N, int K)
{
    extern __shared__ uint32_t ds[];
    const int tid = threadIdx.x, lane = tid & 31;
    const int g = lane >> 2, tg = lane & 3;
    const int w = tid >> 5, wm = w & 3, wn = w >> 2;
    const int row0 = blockIdx.y * 128, col0 = blockIdx.x * 128;

    const int ar = tid >> 3, ac = (tid & 7) * 4;   // A: 32 rows / iter, 4 iters
    const int br = tid >> 5, bc = (tid & 31) * 4;  // B: 8 rows / iter, 4 iters

    float acc[2][8][4];
#pragma unroll
    for (int m = 0; m < 2; m++)
#pragma unroll
        for (int n = 0; n < 8; n++)
#pragma unroll
            for (int c = 0; c < 4; c++) acc[m][n][c] = 0.f;

    uint4 pa[4], pb[4];
#pragma unroll
    for (int it = 0; it < 4; it++) {
        pa[it] = *(const uint4*)&A[(size_t)(row0 + ar + it * 32) * K + ac];
        pb[it] = *(const uint4*)&B[(size_t)(br + it * 8) * N + col0 + bc];
    }
    int buf = 0;
#pragma unroll
    for (int it = 0; it < 4; it++) {
        *(uint4*)&ds[buf * 4608 + (ar + it * 32) * 36 + ac] = pa[it];
        *(uint4*)&ds[9216 + buf * 4224 + (br + it * 8) * 132 + bc] = pb[it];
    }
    __syncthreads();

    for (int k0 = 0; k0 < K; k0 += 32) {
        const bool nxt = (k0 + 32) < K;
        if (nxt) {
#pragma unroll
            for (int it = 0; it < 4; it++) {
                pa[it] = *(const uint4*)&A[(size_t)(row0 + ar + it * 32) * K + k0 + 32 + ac];
                pb[it] = *(const uint4*)&B[(size_t)(k0 + 32 + br + it * 8) * N + col0 + bc];
            }
        }
        const uint32_t* Asb = ds + buf * 4608;
        const uint32_t* Bsb = ds + 9216 + buf * 4224;
#pragma unroll
        for (int kk = 0; kk < 32; kk += 8) {
            uint32_t a[2][4];
#pragma unroll
            for (int mt = 0; mt < 2; mt++) {
                const int r = wm * 32 + mt * 16 + g;
                a[mt][0] = Asb[r * 36 + kk + tg];
                a[mt][1] = Asb[(r + 8) * 36 + kk + tg];
                a[mt][2] = Asb[r * 36 + kk + tg + 4];
                a[mt][3] = Asb[(r + 8) * 36 + kk + tg + 4];
            }
#pragma unroll
            for (int nt = 0; nt < 8; nt++) {
                const int n = wn * 64 + nt * 8 + g;
                uint32_t bf[2];
                bf[0] = Bsb[(kk + tg) * 132 + n];
                bf[1] = Bsb[(kk + tg + 4) * 132 + n];
                mma8(acc[0][nt], a[0], bf);
                mma8(acc[1][nt], a[1], bf);
            }
        }
        if (nxt) {
            buf ^= 1;
#pragma unroll
            for (int it = 0; it < 4; it++) {
                *(uint4*)&ds[buf * 4608 + (ar + it * 32) * 36 + ac] = pa[it];
                *(uint4*)&ds[9216 + buf * 4224 + (br + it * 8) * 132 + bc] = pb[it];
            }
            __syncthreads();
        }
    }

#pragma unroll
    for (int mt = 0; mt < 2; mt++) {
        const int r0 = row0 + wm * 32 + mt * 16 + g;
#pragma unroll
        for (int nt = 0; nt < 8; nt++) {
            const int cc = col0 + wn * 64 + nt * 8 + 2 * tg;
            if (CVT_OUT) {
                *(uint2*)&C[(size_t)r0 * N + cc] =
                    make_uint2(f2tf(acc[mt][nt][0]), f2tf(acc[mt][nt][1]));
                *(uint2*)&C[(size_t)(r0 + 8) * N + cc] =
                    make_uint2(f2tf(acc[mt][nt][2]), f2tf(acc[mt][nt][3]));
            } else {
                *(uint2*)&C[(size_t)r0 * N + cc] =
                    make_uint2(__float_as_uint(acc[mt][nt][0]), __float_as_uint(acc[mt][nt][1]));
                *(uint2*)&C[(size_t)(r0 + 8) * N + cc] =
                    make_uint2(__float_as_uint(acc[mt][nt][2]), __float_as_uint(acc[mt][nt][3]));
            }
        }
    }
}

// ---------------------------------------------------------------------------
// Flash attention on tf32 MMAs. CTA = (b, h, 64-query tile), 256 thr, 8 warps
// in 4(m) x 2(n) grid; warp owns 16 rows x 32 cols of S and of O.
// Smem (88064B): Qs/Ks/Vs/Ps [64][68] tf32 bits, Bb [64][68] fp32 bias,
// rmax/rsum [2][64] cross-warp softmax scratch.
// ---------------------------------------------------------------------------
__global__ __launch_bounds__(256) void flash_attn_tc(
    const uint32_t* __restrict__ qkv, const float* __restrict__ bias,
    const float* __restrict__ beta, uint32_t* __restrict__ att)
{
    extern __shared__ uint32_t sm[];
    uint32_t* Qs = sm;              // [64][68]
    uint32_t* Ks = sm + 4352;
    uint32_t* Vs = sm + 2 * 4352;
    uint32_t* Ps = sm + 3 * 4352;
    float* Bb    = (float*)(sm + 4 * 4352);
    float* rmax  = (float*)(sm + 5 * 4352);  // [2][64]
    float* rsum  = rmax + 128;

    const int qt = blockIdx.x, h = blockIdx.y, b = blockIdx.z;
    const int tid = threadIdx.x, lane = tid & 31;
    const int g = lane >> 2, tg = lane & 3;
    const int w = tid >> 5, wm = w & 3, wn = w >> 2;
    const int r0 = wm * 16 + g, r1 = r0 + 8;
    const bool phys = (h < NPHYS);
    const float bb = phys ? beta[h] : 0.f;

    const size_t qbase = (size_t)(b * SEQ + qt * 64) * QKVCOLS + h * DHEAD;
#pragma unroll
    for (int it = 0; it < 4; it++) {
        int idx = tid + it * 256;
        int i = idx >> 4, d4 = (idx & 15) * 4;
        *(uint4*)&Qs[i * 68 + d4] = *(const uint4*)&qkv[qbase + (size_t)i * QKVCOLS + d4];
    }

    float O[4][4];
    float m0 = -1e30f, m1 = -1e30f, l0 = 0.f, l1 = 0.f;
#pragma unroll
    for (int nt = 0; nt < 4; nt++)
#pragma unroll
        for (int c = 0; c < 4; c++) O[nt][c] = 0.f;

    const float* bias_b = bias + (size_t)b * SEQ * SEQ + (size_t)(qt * 64) * SEQ;

    for (int jt = 0; jt < 32; jt++) {
        __syncthreads();  // prior PV reads of Vs/Ps done; Bb reads done
        const size_t kbase = (size_t)(b * SEQ + jt * 64) * QKVCOLS + h * DHEAD;
#pragma unroll
        for (int it = 0; it < 4; it++) {
            int idx = tid + it * 256;
            int j = idx >> 4, d4 = (idx & 15) * 4;
            *(uint4*)&Ks[j * 68 + d4] =
                *(const uint4*)&qkv[kbase + (size_t)j * QKVCOLS + DMODEL + d4];
            *(uint4*)&Vs[j * 68 + d4] =
                *(const uint4*)&qkv[kbase + (size_t)j * QKVCOLS + 2 * DMODEL + d4];
        }
        if (phys) {
#pragma unroll
            for (int it = 0; it < 4; it++) {
                int idx = tid + it * 256;
                int i = idx >> 4, c4 = (idx & 15) * 4;
                *(float4*)&Bb[i * 68 + c4] =
                    *(const float4*)&bias_b[(size_t)i * SEQ + jt * 64 + c4];
            }
        }
        __syncthreads();

        // ---- S = Q K^T ----
        float S[4][4];
#pragma unroll
        for (int nt = 0; nt < 4; nt++)
#pragma unroll
            for (int c = 0; c < 4; c++) S[nt][c] = 0.f;
#pragma unroll
        for (int kk = 0; kk < 64; kk += 8) {
            uint32_t a[4];
            a[0] = Qs[r0 * 68 + kk + tg];
            a[1] = Qs[r1 * 68 + kk + tg];
            a[2] = Qs[r0 * 68 + kk + tg + 4];
            a[3] = Qs[r1 * 68 + kk + tg + 4];
#pragma unroll
            for (int nt = 0; nt < 4; nt++) {
                const int n = wn * 32 + nt * 8 + g;
                uint32_t bf[2];
                bf[0] = Ks[n * 68 + kk + tg];
                bf[1] = Ks[n * 68 + kk + tg + 4];
                mma8(S[nt], a, bf);
            }
        }

        // scale + additive bias
#pragma unroll
        for (int nt = 0; nt < 4; nt++) {
            S[nt][0] *= 0.125f; S[nt][1] *= 0.125f; S[nt][2] *= 0.125f; S[nt][3] *= 0.125f;
        }
        if (phys) {
#pragma unroll
            for (int nt = 0; nt < 4; nt++) {
                const int cb = wn * 32 + nt * 8 + 2 * tg;
                float2 u = *(float2*)&Bb[r0 * 68 + cb];
                float2 v = *(float2*)&Bb[r1 * 68 + cb];
                S[nt][0] += bb * u.x; S[nt][1] += bb * u.y;
                S[nt][2] += bb * v.x; S[nt][3] += bb * v.y;
            }
        }

        // ---- online softmax ----
        float mx0 = -1e30f, mx1 = -1e30f;
#pragma unroll
        for (int nt = 0; nt < 4; nt++) {
            mx0 = fmaxf(mx0, fmaxf(S[nt][0], S[nt][1]));
            mx1 = fmaxf(mx1, fmaxf(S[nt][2], S[nt][3]));
        }
        mx0 = fmaxf(mx0, __shfl_xor_sync(0xffffffffu, mx0, 1));
        mx0 = fmaxf(mx0, __shfl_xor_sync(0xffffffffu, mx0, 2));
        mx1 = fmaxf(mx1, __shfl_xor_sync(0xffffffffu, mx1, 1));
        mx1 = fmaxf(mx1, __shfl_xor_sync(0xffffffffu, mx1, 2));
        if (tg == 0) { rmax[wn * 64 + r0] = mx0; rmax[wn * 64 + r1] = mx1; }
        __syncthreads();
        mx0 = fmaxf(mx0, rmax[(wn ^ 1) * 64 + r0]);
        mx1 = fmaxf(mx1, rmax[(wn ^ 1) * 64 + r1]);
        const float mn0 = fmaxf(m0, mx0), mn1 = fmaxf(m1, mx1);
        const float c0 = __expf(m0 - mn0), c1 = __expf(m1 - mn1);
        float rs0 = 0.f, rs1 = 0.f;
#pragma unroll
        for (int nt = 0; nt < 4; nt++) {
            const float p00 = __expf(S[nt][0] - mn0), p01 = __expf(S[nt][1] - mn0);
            const float p10 = __expf(S[nt][2] - mn1), p11 = __expf(S[nt][3] - mn1);
            rs0 += p00 + p01; rs1 += p10 + p11;
            const int cb = wn * 32 + nt * 8 + 2 * tg;
            *(uint2*)&Ps[r0 * 68 + cb] = make_uint2(f2tf(p00), f2tf(p01));
            *(uint2*)&Ps[r1 * 68 + cb] = make_uint2(f2tf(p10), f2tf(p11));
        }
        rs0 += __shfl_xor_sync(0xffffffffu, rs0, 1);
        rs0 += __shfl_xor_sync(0xffffffffu, rs0, 2);
        rs1 += __shfl_xor_sync(0xffffffffu, rs1, 1);
        rs1 += __shfl_xor_sync(0xffffffffu, rs1, 2);
        if (tg == 0) { rsum[wn * 64 + r0] = rs0; rsum[wn * 64 + r1] = rs1; }
#pragma unroll
        for (int nt = 0; nt < 4; nt++) {
            O[nt][0] *= c0; O[nt][1] *= c0; O[nt][2] *= c1; O[nt][3] *= c1;
        }
        m0 = mn0; m1 = mn1;
        __syncthreads();   // rsum + Ps visible
        rs0 += rsum[(wn ^ 1) * 64 + r0];
        rs1 += rsum[(wn ^ 1) * 64 + r1];
        l0 = l0 * c0 + rs0;
        l1 = l1 * c1 + rs1;

        // ---- O += P V ----
#pragma unroll
        for (int kk = 0; kk < 64; kk += 8) {
            uint32_t a[4];
            a[0] = Ps[r0 * 68 + kk + tg];
            a[1] = Ps[r1 * 68 + kk + tg];
            a[2] = Ps[r0 * 68 + kk + tg + 4];
            a[3] = Ps[r1 * 68 + kk + tg + 4];
#pragma unroll
            for (int nt = 0; nt < 4; nt++) {
                const int n = wn * 32 + nt * 8 + g;
                uint32_t bf[2];
                bf[0] = Vs[(kk + tg) * 68 + n];
                bf[1] = Vs[(kk + tg + 4) * 68 + n];
                mma8(O[nt], a, bf);
            }
        }
    }

    const float i0 = 1.f / l0, i1 = 1.f / l1;
    const size_t obase = (size_t)(b * SEQ + qt * 64) * DMODEL + h * DHEAD;
#pragma unroll
    for (int nt = 0; nt < 4; nt++) {
        const int cc = wn * 32 + nt * 8 + 2 * tg;
        *(uint2*)&att[obase + (size_t)r0 * DMODEL + cc] =
            make_uint2(f2tf(O[nt][0] * i0), f2tf(O[nt][1] * i0));
        *(uint2*)&att[obase + (size_t)r1 * DMODEL + cc] =
            make_uint2(f2tf(O[nt][2] * i1), f2tf(O[nt][3] * i1));
    }
}

// ---------------------------------------------------------------------------
extern "C" void kernel_launch(void* const* d_in, const int* in_sizes, int n_in,
                              void* d_out, int out_size)
{
    const float* x         = (const float*)d_in[0];  // [2,2048,1024]
    const float* attn_bias = (const float*)d_in[1];  // [2,1,2048,2048]
    const float* Wqkv      = (const float*)d_in[2];  // [1024,3072]
    const float* Wproj     = (const float*)d_in[3];  // [1024,1024]
    const float* beta      = (const float*)d_in[4];  // [8]
    float* out = (float*)d_out;                      // [2,2048,1024]

    uint32_t *xc, *wqkvc, *wprojc, *qkvc, *attc;
    cudaGetSymbolAddress((void**)&xc, g_xc);
    cudaGetSymbolAddress((void**)&wqkvc, g_wqkvc);
    cudaGetSymbolAddress((void**)&wprojc, g_wprojc);
    cudaGetSymbolAddress((void**)&qkvc, g_qkv);
    cudaGetSymbolAddress((void**)&attc, g_att);

    cudaFuncSetAttribute(gemm_tc<true>,  cudaFuncAttributeMaxDynamicSharedMemorySize, 70656);
    cudaFuncSetAttribute(gemm_tc<false>, cudaFuncAttributeMaxDynamicSharedMemorySize, 70656);
    cudaFuncSetAttribute(flash_attn_tc,  cudaFuncAttributeMaxDynamicSharedMemorySize, 88064);

    // 0) one-time-per-call tf32 rounding of the fp32 inputs
    {
        int n4;
        n4 = ROWS * DMODEL / 4;
        cvt_tf32_kernel<<<(n4 + 255) / 256, 256>>>((const float4*)x, (uint4*)xc, n4);
        n4 = DMODEL * QKVCOLS / 4;
        cvt_tf32_kernel<<<(n4 + 255) / 256, 256>>>((const float4*)Wqkv, (uint4*)wqkvc, n4);
        n4 = DMODEL * DMODEL / 4;
        cvt_tf32_kernel<<<(n4 + 255) / 256, 256>>>((const float4*)Wproj, (uint4*)wprojc, n4);
    }

    // 1) qkv = x @ Wqkv  (tf32 MMA, emits tf32 bits)
    gemm_tc<true><<<dim3(QKVCOLS / 128, ROWS / 128), 256, 70656>>>(
        xc, wqkvc, qkvc, ROWS, QKVCOLS, DMODEL);

    // 2) flash attention (tf32 MMA), emits tf32 bits head-major
    flash_attn_tc<<<dim3(SEQ / 64, NHEADS, BATCH), 256, 88064>>>(
        qkvc, attn_bias, beta, attc);

    // 3) out = att @ Wproj (tf32 MMA, emits fp32)
    gemm_tc<false><<<dim3(DMODEL / 128, ROWS / 128), 256, 70656>>>(
        attc, wprojc, (uint32_t*)out, ROWS, DMODEL, DMODEL);
}

// round 7
// speedup vs baseline: 1.2429x; 1.2429x over previous
#include <cuda_runtime.h>
#include <cstdint>
#include <cstddef>

#define BATCH   2
#define SEQ     2048
#define DMODEL  1024
#define NHEADS  16
#define NPHYS   8
#define DHEAD   64
#define ROWS    (BATCH * SEQ)          // 4096
#define QKVCOLS (3 * DMODEL)           // 3072

// Scratch (device globals: allocation-free contract). tf32-bit arrays as uint32.
__device__ uint32_t g_xc[(size_t)ROWS * DMODEL];
__device__ uint32_t g_wqkvc[(size_t)DMODEL * QKVCOLS];
__device__ uint32_t g_wprojc[(size_t)DMODEL * DMODEL];
__device__ uint32_t g_qkv[(size_t)ROWS * QKVCOLS];
__device__ uint32_t g_att[(size_t)ROWS * DMODEL];

__device__ __forceinline__ uint32_t f2tf(float x) {
    uint32_t r; asm("cvt.rna.tf32.f32 %0, %1;" : "=r"(r) : "f"(x)); return r;
}

// m16n8k8 tf32 MMA, D = A*B + D (in place)
__device__ __forceinline__ void mma8(float* c, const uint32_t* a, const uint32_t* b) {
    asm volatile(
        "mma.sync.aligned.m16n8k8.row.col.f32.tf32.tf32.f32 "
        "{%0,%1,%2,%3},{%4,%5,%6,%7},{%8,%9},{%0,%1,%2,%3};"
        : "+f"(c[0]), "+f"(c[1]), "+f"(c[2]), "+f"(c[3])
        : "r"(a[0]), "r"(a[1]), "r"(a[2]), "r"(a[3]), "r"(b[0]), "r"(b[1]));
}

__device__ __forceinline__ void cp16(uint32_t dst, const void* src) {
    asm volatile("cp.async.ca.shared.global [%0], [%1], 16;" :: "r"(dst), "l"(src) : "memory");
}
#define CP_COMMIT() asm volatile("cp.async.commit_group;" ::: "memory")
#define CP_WAIT0()  asm volatile("cp.async.wait_group 0;" ::: "memory")

// ---------------------------------------------------------------------------
// fp32 -> tf32-bits conversion (vectorized)
// ---------------------------------------------------------------------------
__global__ void cvt_tf32_kernel(const float4* __restrict__ in, uint4* __restrict__ out, int n4) {
    int i = blockIdx.x * blockDim.x + threadIdx.x;
    if (i < n4) {
        float4 v = in[i];
        out[i] = make_uint4(f2tf(v.x), f2tf(v.y), f2tf(v.z), f2tf(v.w));
    }
}

// ---------------------------------------------------------------------------
// tf32 GEMM: C[M,N] = A[M,K] @ B[K,N]. 128 threads = 4 warps, warp grid 2x2,
// warp tile 64x64 (4 m-tiles x 8 n-tiles), BK=32, cp.async double buffer.
// Smem: A[2][128][36] (m-major, pad4) + B[2][32][136] (k-major, pad8) = 71680B.
// ---------------------------------------------------------------------------
template<bool CVT_OUT>
__global__ __launch_bounds__(128) void gemm_tc(
    const uint32_t* __restrict__ A, const uint32_t* __restrict__ B, uint32_t* __restrict__ C,
    int M, int N, int K)
{
    extern __shared__ uint32_t ds[];
    const int tid = threadIdx.x, lane = tid & 31;
    const int g = lane >> 2, tg = lane & 3;
    const int w = tid >> 5, wm = w & 1, wn = w >> 1;
    const int row0 = blockIdx.y * 128, col0 = blockIdx.x * 128;

    const uint32_t sbase = (uint32_t)__cvta_generic_to_shared(ds);

    float acc[4][8][4];
#pragma unroll
    for (int mt = 0; mt < 4; mt++)
#pragma unroll
        for (int nt = 0; nt < 8; nt++)
#pragma unroll
            for (int c = 0; c < 4; c++) acc[mt][nt][c] = 0.f;

    auto issue_tile = [&](int buf, int k0) {
#pragma unroll
        for (int i = 0; i < 8; i++) {               // A tile: 128 rows x 32 cols
            int s = tid + i * 128;
            int r = s >> 3, c4 = (s & 7) * 4;
            cp16(sbase + (uint32_t)(buf * 4608 + r * 36 + c4) * 4,
                 A + (size_t)(row0 + r) * K + k0 + c4);
        }
#pragma unroll
        for (int i = 0; i < 8; i++) {               // B tile: 32 rows x 128 cols
            int s = tid + i * 128;
            int r = s >> 5, c4 = (s & 31) * 4;
            cp16(sbase + (uint32_t)(9216 + buf * 4352 + r * 136 + c4) * 4,
                 B + (size_t)(k0 + r) * N + col0 + c4);
        }
    };

    issue_tile(0, 0);
    CP_COMMIT();
    CP_WAIT0();
    __syncthreads();

    int buf = 0;
    for (int k0 = 0; k0 < K; k0 += 32) {
        const bool nxt = (k0 + 32) < K;
        if (nxt) { issue_tile(buf ^ 1, k0 + 32); CP_COMMIT(); }

        const uint32_t* Asb = ds + buf * 4608;
        const uint32_t* Bsb = ds + 9216 + buf * 4352;
#pragma unroll
        for (int kk = 0; kk < 32; kk += 8) {
            uint32_t a[4][4];
#pragma unroll
            for (int mt = 0; mt < 4; mt++) {
                const int r = wm * 64 + mt * 16 + g;
                a[mt][0] = Asb[r * 36 + kk + tg];
                a[mt][1] = Asb[(r + 8) * 36 + kk + tg];
                a[mt][2] = Asb[r * 36 + kk + tg + 4];
                a[mt][3] = Asb[(r + 8) * 36 + kk + tg + 4];
            }
#pragma unroll
            for (int nt = 0; nt < 8; nt++) {
                const int n = wn * 64 + nt * 8 + g;
                uint32_t bf[2];
                bf[0] = Bsb[(kk + tg) * 136 + n];
                bf[1] = Bsb[(kk + tg + 4) * 136 + n];
#pragma unroll
                for (int mt = 0; mt < 4; mt++) mma8(acc[mt][nt], a[mt], bf);
            }
        }
        if (nxt) { CP_WAIT0(); __syncthreads(); buf ^= 1; }
    }

#pragma unroll
    for (int mt = 0; mt < 4; mt++) {
        const int r0 = row0 + wm * 64 + mt * 16 + g;
#pragma unroll
        for (int nt = 0; nt < 8; nt++) {
            const int cc = col0 + wn * 64 + nt * 8 + 2 * tg;
            if (CVT_OUT) {
                *(uint2*)&C[(size_t)r0 * N + cc] =
                    make_uint2(f2tf(acc[mt][nt][0]), f2tf(acc[mt][nt][1]));
                *(uint2*)&C[(size_t)(r0 + 8) * N + cc] =
                    make_uint2(f2tf(acc[mt][nt][2]), f2tf(acc[mt][nt][3]));
            } else {
                *(uint2*)&C[(size_t)r0 * N + cc] =
                    make_uint2(__float_as_uint(acc[mt][nt][0]), __float_as_uint(acc[mt][nt][1]));
                *(uint2*)&C[(size_t)(r0 + 8) * N + cc] =
                    make_uint2(__float_as_uint(acc[mt][nt][2]), __float_as_uint(acc[mt][nt][3]));
            }
        }
    }
}

// ---------------------------------------------------------------------------
// Flash attention, tf32 MMA. CTA = (b, h, 128-query tile), 256 thr, 8 warps
// in 4(m) x 2(n); warp tile 32 rows x 32 cols. Key tile 64.
// Smem (107520B): Qs[128][68] (pre-scaled), Ks[64][68], Vs[64][72],
// PB[128][68] (bias then P, per-thread-identical addresses), rmax/rsum[2][128].
// ---------------------------------------------------------------------------
__global__ __launch_bounds__(256) void flash_attn_tc(
    const uint32_t* __restrict__ qkv, const float* __restrict__ bias,
    const float* __restrict__ beta, uint32_t* __restrict__ att)
{
    extern __shared__ uint32_t sm[];
    uint32_t* Qs = sm;                      // [128][68]
    uint32_t* Ks = sm + 8704;               // [64][68]
    uint32_t* Vs = sm + 13056;              // [64][72]
    uint32_t* PB = sm + 17664;              // [128][68]
    float* rmax  = (float*)(sm + 26368);    // [2][128]
    float* rsum  = rmax + 256;

    const int qt = blockIdx.x, h = blockIdx.y, b = blockIdx.z;
    const int tid = threadIdx.x, lane = tid & 31;
    const int g = lane >> 2, tg = lane & 3;
    const int w = tid >> 5, wm = w & 3, wn = w >> 2;
    const bool phys = (h < NPHYS);
    const float bb = phys ? beta[h] : 0.f;

    // Q load, pre-scaled by 1/8 (exponent-only: exact for tf32 bit patterns)
    const size_t qbase = (size_t)(b * SEQ + qt * 128) * QKVCOLS + h * DHEAD;
#pragma unroll
    for (int it = 0; it < 8; it++) {
        int idx = tid + it * 256;           // 2048 uint4 slots (128 x 16)
        int i = idx >> 4, d4 = (idx & 15) * 4;
        uint4 v = *(const uint4*)&qkv[qbase + (size_t)i * QKVCOLS + d4];
        v.x = __float_as_uint(__uint_as_float(v.x) * 0.125f);
        v.y = __float_as_uint(__uint_as_float(v.y) * 0.125f);
        v.z = __float_as_uint(__uint_as_float(v.z) * 0.125f);
        v.w = __float_as_uint(__uint_as_float(v.w) * 0.125f);
        *(uint4*)&Qs[i * 68 + d4] = v;
    }

    float O[2][4][4], m[2][2], l[2][2];
#pragma unroll
    for (int mt = 0; mt < 2; mt++) {
        m[mt][0] = m[mt][1] = -1e30f;
        l[mt][0] = l[mt][1] = 0.f;
#pragma unroll
        for (int nt = 0; nt < 4; nt++)
#pragma unroll
            for (int c = 0; c < 4; c++) O[mt][nt][c] = 0.f;
    }

    const float* bias_b = bias + (size_t)b * SEQ * SEQ + (size_t)(qt * 128) * SEQ;

    for (int jt = 0; jt < 32; jt++) {
        __syncthreads();  // previous PV reads of Vs/PB complete
        const size_t kb = (size_t)(b * SEQ + jt * 64) * QKVCOLS + h * DHEAD;
#pragma unroll
        for (int it = 0; it < 4; it++) {
            int idx = tid + it * 256;       // 1024 slots (64 x 16)
            int j = idx >> 4, d4 = (idx & 15) * 4;
            *(uint4*)&Ks[j * 68 + d4] =
                *(const uint4*)&qkv[kb + (size_t)j * QKVCOLS + DMODEL + d4];
            *(uint4*)&Vs[j * 72 + d4] =
                *(const uint4*)&qkv[kb + (size_t)j * QKVCOLS + 2 * DMODEL + d4];
        }
        if (phys) {
#pragma unroll
            for (int it = 0; it < 8; it++) {
                int idx = tid + it * 256;   // 2048 slots (128 x 16)
                int i = idx >> 4, c4 = (idx & 15) * 4;
                *(float4*)&((float*)PB)[i * 68 + c4] =
                    *(const float4*)&bias_b[(size_t)i * SEQ + jt * 64 + c4];
            }
        }
        __syncthreads();

        // ---- S = (Q/8) K^T ----
        float S[2][4][4];
#pragma unroll
        for (int mt = 0; mt < 2; mt++)
#pragma unroll
            for (int nt = 0; nt < 4; nt++)
#pragma unroll
                for (int c = 0; c < 4; c++) S[mt][nt][c] = 0.f;
#pragma unroll
        for (int kk = 0; kk < 64; kk += 8) {
            uint32_t a[2][4];
#pragma unroll
            for (int mt = 0; mt < 2; mt++) {
                const int r = wm * 32 + mt * 16 + g;
                a[mt][0] = Qs[r * 68 + kk + tg];
                a[mt][1] = Qs[(r + 8) * 68 + kk + tg];
                a[mt][2] = Qs[r * 68 + kk + tg + 4];
                a[mt][3] = Qs[(r + 8) * 68 + kk + tg + 4];
            }
#pragma unroll
            for (int nt = 0; nt < 4; nt++) {
                const int n = wn * 32 + nt * 8 + g;
                uint32_t bf[2];
                bf[0] = Ks[n * 68 + kk + tg];
                bf[1] = Ks[n * 68 + kk + tg + 4];
                mma8(S[0][nt], a[0], bf);
                mma8(S[1][nt], a[1], bf);
            }
        }

        if (phys) {
#pragma unroll
            for (int mt = 0; mt < 2; mt++) {
                const int r0 = wm * 32 + mt * 16 + g, r1 = r0 + 8;
#pragma unroll
                for (int nt = 0; nt < 4; nt++) {
                    const int cb = wn * 32 + nt * 8 + 2 * tg;
                    float2 u = *(float2*)&((float*)PB)[r0 * 68 + cb];
                    float2 v = *(float2*)&((float*)PB)[r1 * 68 + cb];
                    S[mt][nt][0] += bb * u.x; S[mt][nt][1] += bb * u.y;
                    S[mt][nt][2] += bb * v.x; S[mt][nt][3] += bb * v.y;
                }
            }
        }

        // ---- online softmax ----
        float mx[2][2];
#pragma unroll
        for (int mt = 0; mt < 2; mt++) {
            float m0 = -1e30f, m1 = -1e30f;
#pragma unroll
            for (int nt = 0; nt < 4; nt++) {
                m0 = fmaxf(m0, fmaxf(S[mt][nt][0], S[mt][nt][1]));
                m1 = fmaxf(m1, fmaxf(S[mt][nt][2], S[mt][nt][3]));
            }
            m0 = fmaxf(m0, __shfl_xor_sync(0xffffffffu, m0, 1));
            m0 = fmaxf(m0, __shfl_xor_sync(0xffffffffu, m0, 2));
            m1 = fmaxf(m1, __shfl_xor_sync(0xffffffffu, m1, 1));
            m1 = fmaxf(m1, __shfl_xor_sync(0xffffffffu, m1, 2));
            mx[mt][0] = m0; mx[mt][1] = m1;
        }
        if (tg == 0) {
#pragma unroll
            for (int mt = 0; mt < 2; mt++) {
                const int r0 = wm * 32 + mt * 16 + g;
                rmax[wn * 128 + r0] = mx[mt][0];
                rmax[wn * 128 + r0 + 8] = mx[mt][1];
            }
        }
        __syncthreads();

        float corr[2][2], rs[2][2];
#pragma unroll
        for (int mt = 0; mt < 2; mt++) {
            const int r0 = wm * 32 + mt * 16 + g, r1 = r0 + 8;
            const float q0 = fmaxf(mx[mt][0], rmax[(wn ^ 1) * 128 + r0]);
            const float q1 = fmaxf(mx[mt][1], rmax[(wn ^ 1) * 128 + r1]);
            const float mn0 = fmaxf(m[mt][0], q0), mn1 = fmaxf(m[mt][1], q1);
            corr[mt][0] = __expf(m[mt][0] - mn0);
            corr[mt][1] = __expf(m[mt][1] - mn1);
            m[mt][0] = mn0; m[mt][1] = mn1;
            float s0 = 0.f, s1 = 0.f;
#pragma unroll
            for (int nt = 0; nt < 4; nt++) {
                const float p00 = __expf(S[mt][nt][0] - mn0), p01 = __expf(S[mt][nt][1] - mn0);
                const float p10 = __expf(S[mt][nt][2] - mn1), p11 = __expf(S[mt][nt][3] - mn1);
                s0 += p00 + p01; s1 += p10 + p11;
                const int cb = wn * 32 + nt * 8 + 2 * tg;
                *(uint2*)&PB[r0 * 68 + cb] = make_uint2(f2tf(p00), f2tf(p01));
                *(uint2*)&PB[r1 * 68 + cb] = make_uint2(f2tf(p10), f2tf(p11));
            }
            s0 += __shfl_xor_sync(0xffffffffu, s0, 1);
            s0 += __shfl_xor_sync(0xffffffffu, s0, 2);
            s1 += __shfl_xor_sync(0xffffffffu, s1, 1);
            s1 += __shfl_xor_sync(0xffffffffu, s1, 2);
            rs[mt][0] = s0; rs[mt][1] = s1;
        }
        if (tg == 0) {
#pragma unroll
            for (int mt = 0; mt < 2; mt++) {
                const int r0 = wm * 32 + mt * 16 + g;
                rsum[wn * 128 + r0] = rs[mt][0];
                rsum[wn * 128 + r0 + 8] = rs[mt][1];
            }
        }
#pragma unroll
        for (int mt = 0; mt < 2; mt++)
#pragma unroll
            for (int nt = 0; nt < 4; nt++) {
                O[mt][nt][0] *= corr[mt][0]; O[mt][nt][1] *= corr[mt][0];
                O[mt][nt][2] *= corr[mt][1]; O[mt][nt][3] *= corr[mt][1];
            }
        __syncthreads();   // P + rsum visible
#pragma unroll
        for (int mt = 0; mt < 2; mt++) {
            const int r0 = wm * 32 + mt * 16 + g;
            l[mt][0] = l[mt][0] * corr[mt][0] + rs[mt][0] + rsum[(wn ^ 1) * 128 + r0];
            l[mt][1] = l[mt][1] * corr[mt][1] + rs[mt][1] + rsum[(wn ^ 1) * 128 + r0 + 8];
        }

        // ---- O += P V ----
#pragma unroll
        for (int kk = 0; kk < 64; kk += 8) {
            uint32_t a[2][4];
#pragma unroll
            for (int mt = 0; mt < 2; mt++) {
                const int r = wm * 32 + mt * 16 + g;
                a[mt][0] = PB[r * 68 + kk + tg];
                a[mt][1] = PB[(r + 8) * 68 + kk + tg];
                a[mt][2] = PB[r * 68 + kk + tg + 4];
                a[mt][3] = PB[(r + 8) * 68 + kk + tg + 4];
            }
#pragma unroll
            for (int nt = 0; nt < 4; nt++) {
                const int n = wn * 32 + nt * 8 + g;
                uint32_t bf[2];
                bf[0] = Vs[(kk + tg) * 72 + n];
                bf[1] = Vs[(kk + tg + 4) * 72 + n];
                mma8(O[0][nt], a[0], bf);
                mma8(O[1][nt], a[1], bf);
            }
        }
    }

    const size_t obase = (size_t)(b * SEQ + qt * 128) * DMODEL + h * DHEAD;
#pragma unroll
    for (int mt = 0; mt < 2; mt++) {
        const int r0 = wm * 32 + mt * 16 + g, r1 = r0 + 8;
        const float i0 = 1.f / l[mt][0], i1 = 1.f / l[mt][1];
#pragma unroll
        for (int nt = 0; nt < 4; nt++) {
            const int cc = wn * 32 + nt * 8 + 2 * tg;
            *(uint2*)&att[obase + (size_t)r0 * DMODEL + cc] =
                make_uint2(f2tf(O[mt][nt][0] * i0), f2tf(O[mt][nt][1] * i0));
            *(uint2*)&att[obase + (size_t)r1 * DMODEL + cc] =
                make_uint2(f2tf(O[mt][nt][2] * i1), f2tf(O[mt][nt][3] * i1));
        }
    }
}

// ---------------------------------------------------------------------------
extern "C" void kernel_launch(void* const* d_in, const int* in_sizes, int n_in,
                              void* d_out, int out_size)
{
    const float* x         = (const float*)d_in[0];
    const float* attn_bias = (const float*)d_in[1];
    const float* Wqkv      = (const float*)d_in[2];
    const float* Wproj     = (const float*)d_in[3];
    const float* beta      = (const float*)d_in[4];
    float* out = (float*)d_out;

    uint32_t *xc, *wqkvc, *wprojc, *qkvc, *attc;
    cudaGetSymbolAddress((void**)&xc, g_xc);
    cudaGetSymbolAddress((void**)&wqkvc, g_wqkvc);
    cudaGetSymbolAddress((void**)&wprojc, g_wprojc);
    cudaGetSymbolAddress((void**)&qkvc, g_qkv);
    cudaGetSymbolAddress((void**)&attc, g_att);

    cudaFuncSetAttribute(gemm_tc<true>,  cudaFuncAttributeMaxDynamicSharedMemorySize, 71680);
    cudaFuncSetAttribute(gemm_tc<false>, cudaFuncAttributeMaxDynamicSharedMemorySize, 71680);
    cudaFuncSetAttribute(flash_attn_tc,  cudaFuncAttributeMaxDynamicSharedMemorySize, 107520);

    {
        int n4;
        n4 = ROWS * DMODEL / 4;
        cvt_tf32_kernel<<<(n4 + 255) / 256, 256>>>((const float4*)x, (uint4*)xc, n4);
        n4 = DMODEL * QKVCOLS / 4;
        cvt_tf32_kernel<<<(n4 + 255) / 256, 256>>>((const float4*)Wqkv, (uint4*)wqkvc, n4);
        n4 = DMODEL * DMODEL / 4;
        cvt_tf32_kernel<<<(n4 + 255) / 256, 256>>>((const float4*)Wproj, (uint4*)wprojc, n4);
    }

    // 1) qkv = x @ Wqkv (emits tf32 bits)
    gemm_tc<true><<<dim3(QKVCOLS / 128, ROWS / 128), 128, 71680>>>(
        xc, wqkvc, qkvc, ROWS, QKVCOLS, DMODEL);

    // 2) flash attention (128-row q-tiles), emits tf32 bits head-major
    flash_attn_tc<<<dim3(SEQ / 128, NHEADS, BATCH), 256, 107520>>>(
        qkvc, attn_bias, beta, attc);

    // 3) out = att @ Wproj (emits fp32)
    gemm_tc<false><<<dim3(DMODEL / 128, ROWS / 128), 128, 71680>>>(
        attc, wprojc, (uint32_t*)out, ROWS, DMODEL, DMODEL);
}

// round 9
// speedup vs baseline: 1.2462x; 1.0027x over previous
#include <cuda_runtime.h>
#include <cstdint>
#include <cstddef>

#define BATCH   2
#define SEQ     2048
#define DMODEL  1024
#define NHEADS  16
#define NPHYS   8
#define DHEAD   64
#define ROWS    (BATCH * SEQ)          // 4096
#define QKVCOLS (3 * DMODEL)           // 3072

// Scratch (device globals: allocation-free contract). tf32-bit arrays as uint32.
__device__ uint32_t g_xc[(size_t)ROWS * DMODEL];
__device__ uint32_t g_wqkvc[(size_t)DMODEL * QKVCOLS];
__device__ uint32_t g_wprojc[(size_t)DMODEL * DMODEL];
__device__ uint32_t g_qkv[(size_t)ROWS * QKVCOLS];
__device__ uint32_t g_att[(size_t)ROWS * DMODEL];

__device__ __forceinline__ uint32_t f2tf(float x) {
    uint32_t r; asm("cvt.rna.tf32.f32 %0, %1;" : "=r"(r) : "f"(x)); return r;
}

// m16n8k8 tf32 MMA, D = A*B + D (in place)
__device__ __forceinline__ void mma8(float* c, const uint32_t* a, const uint32_t* b) {
    asm volatile(
        "mma.sync.aligned.m16n8k8.row.col.f32.tf32.tf32.f32 "
        "{%0,%1,%2,%3},{%4,%5,%6,%7},{%8,%9},{%0,%1,%2,%3};"
        : "+f"(c[0]), "+f"(c[1]), "+f"(c[2]), "+f"(c[3])
        : "r"(a[0]), "r"(a[1]), "r"(a[2]), "r"(a[3]), "r"(b[0]), "r"(b[1]));
}

__device__ __forceinline__ void cp16(uint32_t dst, const void* src) {
    asm volatile("cp.async.ca.shared.global [%0], [%1], 16;" :: "r"(dst), "l"(src) : "memory");
}
#define CP_COMMIT() asm volatile("cp.async.commit_group;" ::: "memory")
#define CP_WAIT0()  asm volatile("cp.async.wait_group 0;" ::: "memory")

// ---------------------------------------------------------------------------
// fp32 -> tf32-bits conversion (vectorized)
// ---------------------------------------------------------------------------
__global__ void cvt_tf32_kernel(const float4* __restrict__ in, uint4* __restrict__ out, int n4) {
    int i = blockIdx.x * blockDim.x + threadIdx.x;
    if (i < n4) {
        float4 v = in[i];
        out[i] = make_uint4(f2tf(v.x), f2tf(v.y), f2tf(v.z), f2tf(v.w));
    }
}

// ---------------------------------------------------------------------------
// tf32 GEMM: C[M,N] = A[M,K] @ B[K,N]. 128 threads = 4 warps, warp grid 2x2,
// warp tile 64x64 (4 m-tiles x 8 n-tiles), BK=32, cp.async double buffer.
// Smem: A[2][128][36] (m-major, pad4) + B[2][32][136] (k-major, pad8) = 71680B.
// ---------------------------------------------------------------------------
template<bool CVT_OUT>
__global__ __launch_bounds__(128) void gemm_tc(
    const uint32_t* __restrict__ A, const uint32_t* __restrict__ B, uint32_t* __restrict__ C,
    int M, int N, int K)
{
    extern __shared__ uint32_t ds[];
    const int tid = threadIdx.x, lane = tid & 31;
    const int g = lane >> 2, tg = lane & 3;
    const int w = tid >> 5, wm = w & 1, wn = w >> 1;
    const int row0 = blockIdx.y * 128, col0 = blockIdx.x * 128;

    const uint32_t sbase = (uint32_t)__cvta_generic_to_shared(ds);

    float acc[4][8][4];
#pragma unroll
    for (int mt = 0; mt < 4; mt++)
#pragma unroll
        for (int nt = 0; nt < 8; nt++)
#pragma unroll
            for (int c = 0; c < 4; c++) acc[mt][nt][c] = 0.f;

    auto issue_tile = [&](int buf, int k0) {
#pragma unroll
        for (int i = 0; i < 8; i++) {               // A tile: 128 rows x 32 cols
            int s = tid + i * 128;
            int r = s >> 3, c4 = (s & 7) * 4;
            cp16(sbase + (uint32_t)(buf * 4608 + r * 36 + c4) * 4,
                 A + (size_t)(row0 + r) * K + k0 + c4);
        }
#pragma unroll
        for (int i = 0; i < 8; i++) {               // B tile: 32 rows x 128 cols
            int s = tid + i * 128;
            int r = s >> 5, c4 = (s & 31) * 4;
            cp16(sbase + (uint32_t)(9216 + buf * 4352 + r * 136 + c4) * 4,
                 B + (size_t)(k0 + r) * N + col0 + c4);
        }
    };

    issue_tile(0, 0);
    CP_COMMIT();
    CP_WAIT0();
    __syncthreads();

    int buf = 0;
    for (int k0 = 0; k0 < K; k0 += 32) {
        const bool nxt = (k0 + 32) < K;
        if (nxt) { issue_tile(buf ^ 1, k0 + 32); CP_COMMIT(); }

        const uint32_t* Asb = ds + buf * 4608;
        const uint32_t* Bsb = ds + 9216 + buf * 4352;
#pragma unroll
        for (int kk = 0; kk < 32; kk += 8) {
            uint32_t a[4][4];
#pragma unroll
            for (int mt = 0; mt < 4; mt++) {
                const int r = wm * 64 + mt * 16 + g;
                a[mt][0] = Asb[r * 36 + kk + tg];
                a[mt][1] = Asb[(r + 8) * 36 + kk + tg];
                a[mt][2] = Asb[r * 36 + kk + tg + 4];
                a[mt][3] = Asb[(r + 8) * 36 + kk + tg + 4];
            }
#pragma unroll
            for (int nt = 0; nt < 8; nt++) {
                const int n = wn * 64 + nt * 8 + g;
                uint32_t bf[2];
                bf[0] = Bsb[(kk + tg) * 136 + n];
                bf[1] = Bsb[(kk + tg + 4) * 136 + n];
#pragma unroll
                for (int mt = 0; mt < 4; mt++) mma8(acc[mt][nt], a[mt], bf);
            }
        }
        if (nxt) { CP_WAIT0(); __syncthreads(); buf ^= 1; }
    }

#pragma unroll
    for (int mt = 0; mt < 4; mt++) {
        const int r0 = row0 + wm * 64 + mt * 16 + g;
#pragma unroll
        for (int nt = 0; nt < 8; nt++) {
            const int cc = col0 + wn * 64 + nt * 8 + 2 * tg;
            if (CVT_OUT) {
                *(uint2*)&C[(size_t)r0 * N + cc] =
                    make_uint2(f2tf(acc[mt][nt][0]), f2tf(acc[mt][nt][1]));
                *(uint2*)&C[(size_t)(r0 + 8) * N + cc] =
                    make_uint2(f2tf(acc[mt][nt][2]), f2tf(acc[mt][nt][3]));
            } else {
                *(uint2*)&C[(size_t)r0 * N + cc] =
                    make_uint2(__float_as_uint(acc[mt][nt][0]), __float_as_uint(acc[mt][nt][1]));
                *(uint2*)&C[(size_t)(r0 + 8) * N + cc] =
                    make_uint2(__float_as_uint(acc[mt][nt][2]), __float_as_uint(acc[mt][nt][3]));
            }
        }
    }
}

// ---------------------------------------------------------------------------
// Flash attention, tf32 MMA. CTA = (b, h, 128-query tile), 256 thr, 8 warps
// in 4(m) x 2(n); warp tile 32 rows x 32 cols. Key tile 64.
// Smem (107520B): Qs[128][68] (pre-scaled), Ks[64][68], Vs[64][72],
// PB[128][68] (bias then P, per-thread-identical addresses), rmax/rsum[2][128].
// ---------------------------------------------------------------------------
__global__ __launch_bounds__(256) void flash_attn_tc(
    const uint32_t* __restrict__ qkv, const float* __restrict__ bias,
    const float* __restrict__ beta, uint32_t* __restrict__ att)
{
    extern __shared__ uint32_t sm[];
    uint32_t* Qs = sm;                      // [128][68]
    uint32_t* Ks = sm + 8704;               // [64][68]
    uint32_t* Vs = sm + 13056;              // [64][72]
    uint32_t* PB = sm + 17664;              // [128][68]
    float* rmax  = (float*)(sm + 26368);    // [2][128]
    float* rsum  = rmax + 256;

    const int qt = blockIdx.x, h = blockIdx.y, b = blockIdx.z;
    const int tid = threadIdx.x, lane = tid & 31;
    const int g = lane >> 2, tg = lane & 3;
    const int w = tid >> 5, wm = w & 3, wn = w >> 2;
    const bool phys = (h < NPHYS);
    const float bb = phys ? beta[h] : 0.f;

    // Q load, pre-scaled by 1/8 (exponent-only: exact for tf32 bit patterns)
    const size_t qbase = (size_t)(b * SEQ + qt * 128) * QKVCOLS + h * DHEAD;
#pragma unroll
    for (int it = 0; it < 8; it++) {
        int idx = tid + it * 256;           // 2048 uint4 slots (128 x 16)
        int i = idx >> 4, d4 = (idx & 15) * 4;
        uint4 v = *(const uint4*)&qkv[qbase + (size_t)i * QKVCOLS + d4];
        v.x = __float_as_uint(__uint_as_float(v.x) * 0.125f);
        v.y = __float_as_uint(__uint_as_float(v.y) * 0.125f);
        v.z = __float_as_uint(__uint_as_float(v.z) * 0.125f);
        v.w = __float_as_uint(__uint_as_float(v.w) * 0.125f);
        *(uint4*)&Qs[i * 68 + d4] = v;
    }

    float O[2][4][4], m[2][2], l[2][2];
#pragma unroll
    for (int mt = 0; mt < 2; mt++) {
        m[mt][0] = m[mt][1] = -1e30f;
        l[mt][0] = l[mt][1] = 0.f;
#pragma unroll
        for (int nt = 0; nt < 4; nt++)
#pragma unroll
            for (int c = 0; c < 4; c++) O[mt][nt][c] = 0.f;
    }

    const float* bias_b = bias + (size_t)b * SEQ * SEQ + (size_t)(qt * 128) * SEQ;

    for (int jt = 0; jt < 32; jt++) {
        __syncthreads();  // previous PV reads of Vs/PB complete
        const size_t kb = (size_t)(b * SEQ + jt * 64) * QKVCOLS + h * DHEAD;
#pragma unroll
        for (int it = 0; it < 4; it++) {
            int idx = tid + it * 256;       // 1024 slots (64 x 16)
            int j = idx >> 4, d4 = (idx & 15) * 4;
            *(uint4*)&Ks[j * 68 + d4] =
                *(const uint4*)&qkv[kb + (size_t)j * QKVCOLS + DMODEL + d4];
            *(uint4*)&Vs[j * 72 + d4] =
                *(const uint4*)&qkv[kb + (size_t)j * QKVCOLS + 2 * DMODEL + d4];
        }
        if (phys) {
#pragma unroll
            for (int it = 0; it < 8; it++) {
                int idx = tid + it * 256;   // 2048 slots (128 x 16)
                int i = idx >> 4, c4 = (idx & 15) * 4;
                *(float4*)&((float*)PB)[i * 68 + c4] =
                    *(const float4*)&bias_b[(size_t)i * SEQ + jt * 64 + c4];
            }
        }
        __syncthreads();

        // ---- S = (Q/8) K^T ----
        float S[2][4][4];
#pragma unroll
        for (int mt = 0; mt < 2; mt++)
#pragma unroll
            for (int nt = 0; nt < 4; nt++)
#pragma unroll
                for (int c = 0; c < 4; c++) S[mt][nt][c] = 0.f;
#pragma unroll
        for (int kk = 0; kk < 64; kk += 8) {
            uint32_t a[2][4];
#pragma unroll
            for (int mt = 0; mt < 2; mt++) {
                const int r = wm * 32 + mt * 16 + g;
                a[mt][0] = Qs[r * 68 + kk + tg];
                a[mt][1] = Qs[(r + 8) * 68 + kk + tg];
                a[mt][2] = Qs[r * 68 + kk + tg + 4];
                a[mt][3] = Qs[(r + 8) * 68 + kk + tg + 4];
            }
#pragma unroll
            for (int nt = 0; nt < 4; nt++) {
                const int n = wn * 32 + nt * 8 + g;
                uint32_t bf[2];
                bf[0] = Ks[n * 68 + kk + tg];
                bf[1] = Ks[n * 68 + kk + tg + 4];
                mma8(S[0][nt], a[0], bf);
                mma8(S[1][nt], a[1], bf);
            }
        }

        if (phys) {
#pragma unroll
            for (int mt = 0; mt < 2; mt++) {
                const int r0 = wm * 32 + mt * 16 + g, r1 = r0 + 8;
#pragma unroll
                for (int nt = 0; nt < 4; nt++) {
                    const int cb = wn * 32 + nt * 8 + 2 * tg;
                    float2 u = *(float2*)&((float*)PB)[r0 * 68 + cb];
                    float2 v = *(float2*)&((float*)PB)[r1 * 68 + cb];
                    S[mt][nt][0] += bb * u.x; S[mt][nt][1] += bb * u.y;
                    S[mt][nt][2] += bb * v.x; S[mt][nt][3] += bb * v.y;
                }
            }
        }

        // ---- online softmax ----
        float mx[2][2];
#pragma unroll
        for (int mt = 0; mt < 2; mt++) {
            float m0 = -1e30f, m1 = -1e30f;
#pragma unroll
            for (int nt = 0; nt < 4; nt++) {
                m0 = fmaxf(m0, fmaxf(S[mt][nt][0], S[mt][nt][1]));
                m1 = fmaxf(m1, fmaxf(S[mt][nt][2], S[mt][nt][3]));
            }
            m0 = fmaxf(m0, __shfl_xor_sync(0xffffffffu, m0, 1));
            m0 = fmaxf(m0, __shfl_xor_sync(0xffffffffu, m0, 2));
            m1 = fmaxf(m1, __shfl_xor_sync(0xffffffffu, m1, 1));
            m1 = fmaxf(m1, __shfl_xor_sync(0xffffffffu, m1, 2));
            mx[mt][0] = m0; mx[mt][1] = m1;
        }
        if (tg == 0) {
#pragma unroll
            for (int mt = 0; mt < 2; mt++) {
                const int r0 = wm * 32 + mt * 16 + g;
                rmax[wn * 128 + r0] = mx[mt][0];
                rmax[wn * 128 + r0 + 8] = mx[mt][1];
            }
        }
        __syncthreads();

        float corr[2][2], rs[2][2];
#pragma unroll
        for (int mt = 0; mt < 2; mt++) {
            const int r0 = wm * 32 + mt * 16 + g, r1 = r0 + 8;
            const float q0 = fmaxf(mx[mt][0], rmax[(wn ^ 1) * 128 + r0]);
            const float q1 = fmaxf(mx[mt][1], rmax[(wn ^ 1) * 128 + r1]);
            const float mn0 = fmaxf(m[mt][0], q0), mn1 = fmaxf(m[mt][1], q1);
            corr[mt][0] = __expf(m[mt][0] - mn0);
            corr[mt][1] = __expf(m[mt][1] - mn1);
            m[mt][0] = mn0; m[mt][1] = mn1;
            float s0 = 0.f, s1 = 0.f;
#pragma unroll
            for (int nt = 0; nt < 4; nt++) {
                const float p00 = __expf(S[mt][nt][0] - mn0), p01 = __expf(S[mt][nt][1] - mn0);
                const float p10 = __expf(S[mt][nt][2] - mn1), p11 = __expf(S[mt][nt][3] - mn1);
                s0 += p00 + p01; s1 += p10 + p11;
                const int cb = wn * 32 + nt * 8 + 2 * tg;
                *(uint2*)&PB[r0 * 68 + cb] = make_uint2(f2tf(p00), f2tf(p01));
                *(uint2*)&PB[r1 * 68 + cb] = make_uint2(f2tf(p10), f2tf(p11));
            }
            s0 += __shfl_xor_sync(0xffffffffu, s0, 1);
            s0 += __shfl_xor_sync(0xffffffffu, s0, 2);
            s1 += __shfl_xor_sync(0xffffffffu, s1, 1);
            s1 += __shfl_xor_sync(0xffffffffu, s1, 2);
            rs[mt][0] = s0; rs[mt][1] = s1;
        }
        if (tg == 0) {
#pragma unroll
            for (int mt = 0; mt < 2; mt++) {
                const int r0 = wm * 32 + mt * 16 + g;
                rsum[wn * 128 + r0] = rs[mt][0];
                rsum[wn * 128 + r0 + 8] = rs[mt][1];
            }
        }
#pragma unroll
        for (int mt = 0; mt < 2; mt++)
#pragma unroll
            for (int nt = 0; nt < 4; nt++) {
                O[mt][nt][0] *= corr[mt][0]; O[mt][nt][1] *= corr[mt][0];
                O[mt][nt][2] *= corr[mt][1]; O[mt][nt][3] *= corr[mt][1];
            }
        __syncthreads();   // P + rsum visible
#pragma unroll
        for (int mt = 0; mt < 2; mt++) {
            const int r0 = wm * 32 + mt * 16 + g;
            l[mt][0] = l[mt][0] * corr[mt][0] + rs[mt][0] + rsum[(wn ^ 1) * 128 + r0];
            l[mt][1] = l[mt][1] * corr[mt][1] + rs[mt][1] + rsum[(wn ^ 1) * 128 + r0 + 8];
        }

        // ---- O += P V ----
#pragma unroll
        for (int kk = 0; kk < 64; kk += 8) {
            uint32_t a[2][4];
#pragma unroll
            for (int mt = 0; mt < 2; mt++) {
                const int r = wm * 32 + mt * 16 + g;
                a[mt][0] = PB[r * 68 + kk + tg];
                a[mt][1] = PB[(r + 8) * 68 + kk + tg];
                a[mt][2] = PB[r * 68 + kk + tg + 4];
                a[mt][3] = PB[(r + 8) * 68 + kk + tg + 4];
            }
#pragma unroll
            for (int nt = 0; nt < 4; nt++) {
                const int n = wn * 32 + nt * 8 + g;
                uint32_t bf[2];
                bf[0] = Vs[(kk + tg) * 72 + n];
                bf[1] = Vs[(kk + tg + 4) * 72 + n];
                mma8(O[0][nt], a[0], bf);
                mma8(O[1][nt], a[1], bf);
            }
        }
    }

    const size_t obase = (size_t)(b * SEQ + qt * 128) * DMODEL + h * DHEAD;
#pragma unroll
    for (int mt = 0; mt < 2; mt++) {
        const int r0 = wm * 32 + mt * 16 + g, r1 = r0 + 8;
        const float i0 = 1.f / l[mt][0], i1 = 1.f / l[mt][1];
#pragma unroll
        for (int nt = 0; nt < 4; nt++) {
            const int cc = wn * 32 + nt * 8 + 2 * tg;
            *(uint2*)&att[obase + (size_t)r0 * DMODEL + cc] =
                make_uint2(f2tf(O[mt][nt][0] * i0), f2tf(O[mt][nt][1] * i0));
            *(uint2*)&att[obase + (size_t)r1 * DMODEL + cc] =
                make_uint2(f2tf(O[mt][nt][2] * i1), f2tf(O[mt][nt][3] * i1));
        }
    }
}

// ---------------------------------------------------------------------------
extern "C" void kernel_launch(void* const* d_in, const int* in_sizes, int n_in,
                              void* d_out, int out_size)
{
    const float* x         = (const float*)d_in[0];
    const float* attn_bias = (const float*)d_in[1];
    const float* Wqkv      = (const float*)d_in[2];
    const float* Wproj     = (const float*)d_in[3];
    const float* beta      = (const float*)d_in[4];
    float* out = (float*)d_out;

    uint32_t *xc, *wqkvc, *wprojc, *qkvc, *attc;
    cudaGetSymbolAddress((void**)&xc, g_xc);
    cudaGetSymbolAddress((void**)&wqkvc, g_wqkvc);
    cudaGetSymbolAddress((void**)&wprojc, g_wprojc);
    cudaGetSymbolAddress((void**)&qkvc, g_qkv);
    cudaGetSymbolAddress((void**)&attc, g_att);

    cudaFuncSetAttribute(gemm_tc<true>,  cudaFuncAttributeMaxDynamicSharedMemorySize, 71680);
    cudaFuncSetAttribute(gemm_tc<false>, cudaFuncAttributeMaxDynamicSharedMemorySize, 71680);
    cudaFuncSetAttribute(flash_attn_tc,  cudaFuncAttributeMaxDynamicSharedMemorySize, 107520);

    {
        int n4;
        n4 = ROWS * DMODEL / 4;
        cvt_tf32_kernel<<<(n4 + 255) / 256, 256>>>((const float4*)x, (uint4*)xc, n4);
        n4 = DMODEL * QKVCOLS / 4;
        cvt_tf32_kernel<<<(n4 + 255) / 256, 256>>>((const float4*)Wqkv, (uint4*)wqkvc, n4);
        n4 = DMODEL * DMODEL / 4;
        cvt_tf32_kernel<<<(n4 + 255) / 256, 256>>>((const float4*)Wproj, (uint4*)wprojc, n4);
    }

    // 1) qkv = x @ Wqkv (emits tf32 bits)
    gemm_tc<true><<<dim3(QKVCOLS / 128, ROWS / 128), 128, 71680>>>(
        xc, wqkvc, qkvc, ROWS, QKVCOLS, DMODEL);

    // 2) flash attention (128-row q-tiles), emits tf32 bits head-major
    flash_attn_tc<<<dim3(SEQ / 128, NHEADS, BATCH), 256, 107520>>>(
        qkvc, attn_bias, beta, attc);

    // 3) out = att @ Wproj (emits fp32)
    gemm_tc<false><<<dim3(DMODEL / 128, ROWS / 128), 128, 71680>>>(
        attc, wprojc, (uint32_t*)out, ROWS, DMODEL, DMODEL);
}